// round 1
// baseline (speedup 1.0000x reference)
#include <cuda_runtime.h>
#include <math.h>

#define Nn 10000
#define Ee 160000
#define Ff 4
#define Hh 32
#define Cc 4

// ---------------- scratch (device globals; no allocation allowed) -----------
__device__ float g_Qn[Nn * Hh * Hh];   // per-node Q matrices [N, H, H] (40MB)
__device__ float g_r [Nn * Hh];        // per-node b2 contribution r[n,o]
__device__ float g_xA[Nn * Hh];        // ping-pong node features (pre-relu)
__device__ float g_xB[Nn * Hh];

// ---------------------------------------------------------------------------
// Kernel B: Qn[n, k*32+o] = sum_i relu?(x[n,i]) * w2[k, i*32+o]
// grid = (N/16, 4), block = 256.  col = k*32+o in [0,1024)
// ---------------------------------------------------------------------------
template <int DIN, bool RELU>
__global__ void qn_kernel(const float* __restrict__ x,
                          const float* __restrict__ w2,
                          float* __restrict__ Qn) {
    constexpr int NT = 16;
    __shared__ float xs[NT][DIN];
    const int nbase = blockIdx.x * NT;
    const int col   = blockIdx.y * 256 + threadIdx.x;   // 0..1023

    for (int idx = threadIdx.x; idx < NT * DIN; idx += 256) {
        int t = idx / DIN, i = idx % DIN;
        int n = nbase + t;
        float v = (n < Nn) ? x[n * DIN + i] : 0.f;
        if (RELU) v = fmaxf(v, 0.f);
        xs[t][i] = v;
    }
    __syncthreads();

    const int k = col >> 5, o = col & 31;
    float w2v[DIN];
#pragma unroll
    for (int i = 0; i < DIN; i++)
        w2v[i] = w2[k * (DIN * Hh) + i * Hh + o];

#pragma unroll
    for (int t = 0; t < NT; t++) {
        float acc = 0.f;
#pragma unroll
        for (int i = 0; i < DIN; i++)
            acc = fmaf(xs[t][i], w2v[i], acc);
        int n = nbase + t;
        if (n < Nn) Qn[n * (Hh * Hh) + col] = acc;
    }
}

// ---------------------------------------------------------------------------
// node aux: agg_init[n,o] = x[n]·root[:,o] + bias[o]   (NNConv root term)
//           r[n,o]        = x[n]·b2[:, ... o]          (b2 folded per-src)
// one warp per node, lane = o
// ---------------------------------------------------------------------------
template <int DIN, bool RELU>
__global__ void aux_kernel(const float* __restrict__ x,
                           const float* __restrict__ root,
                           const float* __restrict__ bias,
                           const float* __restrict__ b2,
                           float* __restrict__ agg,
                           float* __restrict__ rbuf) {
    int warp = (blockIdx.x * blockDim.x + threadIdx.x) >> 5;
    int lane = threadIdx.x & 31;
    if (warp >= Nn) return;
    float accA = 0.f, accR = 0.f;
#pragma unroll
    for (int i = 0; i < DIN; i++) {
        float xv = x[warp * DIN + i];
        if (RELU) xv = fmaxf(xv, 0.f);
        accA = fmaf(xv, root[i * Hh + lane], accA);
        accR = fmaf(xv, b2[i * Hh + lane], accR);
    }
    agg [warp * Hh + lane] = accA + bias[lane];
    rbuf[warp * Hh + lane] = accR;
}

// ---------------------------------------------------------------------------
// edge kernel: one warp per edge, lane = o
//   h[k]   = relu(ea0*w1[0,k] + ea1*w1[1,k] + b1[k])
//   msg[o] = r[src,o] + sum_k h[k] * Qn[src, k, o]
//   atomicAdd(agg[dst, o], msg[o])
// ---------------------------------------------------------------------------
__global__ void edge_kernel(const int* __restrict__ ei,
                            const float* __restrict__ ea,
                            const float* __restrict__ w1,
                            const float* __restrict__ b1,
                            const float* __restrict__ Qn,
                            const float* __restrict__ rbuf,
                            float* __restrict__ agg) {
    int warp = (blockIdx.x * blockDim.x + threadIdx.x) >> 5;
    int lane = threadIdx.x & 31;
    if (warp >= Ee) return;

    int src = ei[warp];
    int dst = ei[Ee + warp];
    float ea0 = ea[warp * 2 + 0];
    float ea1 = ea[warp * 2 + 1];

    float h = fmaxf(fmaf(ea0, w1[lane], fmaf(ea1, w1[Hh + lane], b1[lane])), 0.f);

    const float* __restrict__ q = Qn + src * (Hh * Hh) + lane;
    float acc0 = rbuf[src * Hh + lane];
    float acc1 = 0.f;
#pragma unroll
    for (int k = 0; k < Hh; k += 2) {
        float hk0 = __shfl_sync(0xffffffffu, h, k);
        float hk1 = __shfl_sync(0xffffffffu, h, k + 1);
        acc0 = fmaf(hk0, q[(k    ) * Hh], acc0);
        acc1 = fmaf(hk1, q[(k + 1) * Hh], acc1);
    }
    atomicAdd(&agg[dst * Hh + lane], acc0 + acc1);
}

// ---------------------------------------------------------------------------
// final FC + log_softmax: one warp per node, lane = hidden index
// ---------------------------------------------------------------------------
__global__ void fc_kernel(const float* __restrict__ xr,
                          const float* __restrict__ fcw,
                          const float* __restrict__ fcb,
                          float* __restrict__ out) {
    int warp = (blockIdx.x * blockDim.x + threadIdx.x) >> 5;
    int lane = threadIdx.x & 31;
    if (warp >= Nn) return;

    float xv = fmaxf(xr[warp * Hh + lane], 0.f);
    float lg[Cc];
#pragma unroll
    for (int c = 0; c < Cc; c++) {
        float p = xv * fcw[lane * Cc + c];
#pragma unroll
        for (int s = 16; s > 0; s >>= 1)
            p += __shfl_xor_sync(0xffffffffu, p, s);
        lg[c] = p + fcb[c];
    }
    float m = fmaxf(fmaxf(lg[0], lg[1]), fmaxf(lg[2], lg[3]));
    float se = 0.f;
#pragma unroll
    for (int c = 0; c < Cc; c++) se += __expf(lg[c] - m);
    float lse = m + __logf(se);
    if (lane < Cc) out[warp * Cc + lane] = lg[lane] - lse;
}

// ---------------------------------------------------------------------------
extern "C" void kernel_launch(void* const* d_in, const int* in_sizes, int n_in,
                              void* d_out, int out_size) {
    (void)in_sizes; (void)n_in; (void)out_size;

    const float* x  = (const float*)d_in[0];
    const int*   ei = (const int*)  d_in[1];
    const float* ea = (const float*)d_in[2];
    // layer params: base 3 + 6*l : w1, b1, w2, b2, root, bias
    const float* w1[3];  const float* b1[3];  const float* w2[3];
    const float* b2[3];  const float* rt[3];  const float* bs[3];
    for (int l = 0; l < 3; l++) {
        w1[l] = (const float*)d_in[3 + 6 * l + 0];
        b1[l] = (const float*)d_in[3 + 6 * l + 1];
        w2[l] = (const float*)d_in[3 + 6 * l + 2];
        b2[l] = (const float*)d_in[3 + 6 * l + 3];
        rt[l] = (const float*)d_in[3 + 6 * l + 4];
        bs[l] = (const float*)d_in[3 + 6 * l + 5];
    }
    const float* fcw = (const float*)d_in[21];
    const float* fcb = (const float*)d_in[22];
    float* out = (float*)d_out;

    float *Qn, *rbuf, *xA, *xB;
    cudaGetSymbolAddress((void**)&Qn,   g_Qn);
    cudaGetSymbolAddress((void**)&rbuf, g_r);
    cudaGetSymbolAddress((void**)&xA,   g_xA);
    cudaGetSymbolAddress((void**)&xB,   g_xB);

    const dim3 qgrid((Nn + 15) / 16, 4);
    const int  nodeWarpBlocks = (Nn * 32 + 255) / 256;
    const int  edgeBlocks     = (Ee * 32 + 255) / 256;

    // ---------------- layer 0 (din=4, input not relu'd) ----------------
    qn_kernel <Ff, false><<<qgrid, 256>>>(x, w2[0], Qn);
    aux_kernel<Ff, false><<<nodeWarpBlocks, 256>>>(x, rt[0], bs[0], b2[0], xA, rbuf);
    edge_kernel<<<edgeBlocks, 256>>>(ei, ea, w1[0], b1[0], Qn, rbuf, xA);

    // ---------------- layer 1 (din=32, relu on load) --------------------
    qn_kernel <Hh, true><<<qgrid, 256>>>(xA, w2[1], Qn);
    aux_kernel<Hh, true><<<nodeWarpBlocks, 256>>>(xA, rt[1], bs[1], b2[1], xB, rbuf);
    edge_kernel<<<edgeBlocks, 256>>>(ei, ea, w1[1], b1[1], Qn, rbuf, xB);

    // ---------------- layer 2 -------------------------------------------
    qn_kernel <Hh, true><<<qgrid, 256>>>(xB, w2[2], Qn);
    aux_kernel<Hh, true><<<nodeWarpBlocks, 256>>>(xB, rt[2], bs[2], b2[2], xA, rbuf);
    edge_kernel<<<edgeBlocks, 256>>>(ei, ea, w1[2], b1[2], Qn, rbuf, xA);

    // ---------------- FC + log_softmax ----------------------------------
    fc_kernel<<<nodeWarpBlocks, 256>>>(xA, fcw, fcb, out);
}

// round 2
// speedup vs baseline: 1.0606x; 1.0606x over previous
#include <cuda_runtime.h>
#include <math.h>

#define Nn 10000
#define Ee 160000
#define Ff 4
#define Hh 32
#define Cc 4

// ---------------- scratch (device globals; no allocation allowed) -----------
__device__ float g_Qn[Nn * Hh * Hh];       // per-node Q matrices [N, H, H] (40MB)
__device__ float g_r [Nn * Hh];            // per-node b2 contribution r[n,o]
__device__ float g_xA[Nn * Hh];            // ping-pong node features (pre-relu)
__device__ float g_xB[Nn * Hh];
__device__ int    g_cnt[Nn];               // counting sort: histogram
__device__ int    g_cur[Nn];               // counting sort: scatter cursors
__device__ int    g_off[Nn + 1];           // CSR offsets by src
__device__ int    g_sdst[Ee];              // dst sorted by src
__device__ float2 g_sea [Ee];              // edge_attr sorted by src

// ---------------------------------------------------------------------------
// counting sort by src
// ---------------------------------------------------------------------------
__global__ void zero_kernel() {
    int t = blockIdx.x * blockDim.x + threadIdx.x;
    if (t < Nn) { g_cnt[t] = 0; g_cur[t] = 0; }
}

__global__ void hist_kernel(const int* __restrict__ ei) {
    int t = blockIdx.x * blockDim.x + threadIdx.x;
    if (t < Ee) atomicAdd(&g_cnt[ei[t]], 1);
}

__global__ void scan_kernel() {
    __shared__ int partial[1024];
    const int tid = threadIdx.x;
    const int base = tid * 10;                 // 1024*10 = 10240 >= 10000
    int s = 0;
    for (int j = 0; j < 10; j++) {
        int idx = base + j;
        if (idx < Nn) s += g_cnt[idx];
    }
    partial[tid] = s;
    __syncthreads();
    for (int d = 1; d < 1024; d <<= 1) {       // Hillis-Steele inclusive scan
        int v = 0;
        if (tid >= d) v = partial[tid - d];
        __syncthreads();
        if (tid >= d) partial[tid] += v;
        __syncthreads();
    }
    int run = (tid > 0) ? partial[tid - 1] : 0;
    for (int j = 0; j < 10; j++) {
        int idx = base + j;
        if (idx < Nn) { g_off[idx] = run; run += g_cnt[idx]; }
    }
    if (tid == 1023) g_off[Nn] = run;          // == Ee
}

__global__ void scatter_kernel(const int* __restrict__ ei,
                               const float* __restrict__ ea) {
    int t = blockIdx.x * blockDim.x + threadIdx.x;
    if (t >= Ee) return;
    int s = ei[t];
    int p = g_off[s] + atomicAdd(&g_cur[s], 1);
    g_sdst[p] = ei[Ee + t];
    g_sea[p]  = reinterpret_cast<const float2*>(ea)[t];
}

// ---------------------------------------------------------------------------
// qn (layer 0, din=4): Qn[n, k*32+o] = sum_i x[n,i] * w2[k, i*32+o]
// small K -> keep simple version. grid (N/16, 4), block 256.
// ---------------------------------------------------------------------------
__global__ void qn0_kernel(const float* __restrict__ x,
                           const float* __restrict__ w2,
                           float* __restrict__ Qn) {
    constexpr int NT = 16;
    __shared__ float xs[NT][Ff];
    const int nbase = blockIdx.x * NT;
    const int col   = blockIdx.y * 256 + threadIdx.x;

    for (int idx = threadIdx.x; idx < NT * Ff; idx += 256) {
        int t = idx / Ff, i = idx % Ff;
        int n = nbase + t;
        xs[t][i] = (n < Nn) ? x[n * Ff + i] : 0.f;
    }
    __syncthreads();

    const int k = col >> 5, o = col & 31;
    float w2v[Ff];
#pragma unroll
    for (int i = 0; i < Ff; i++)
        w2v[i] = w2[k * (Ff * Hh) + i * Hh + o];

#pragma unroll
    for (int t = 0; t < NT; t++) {
        float acc = 0.f;
#pragma unroll
        for (int i = 0; i < Ff; i++)
            acc = fmaf(xs[t][i], w2v[i], acc);
        int n = nbase + t;
        if (n < Nn) Qn[n * (Hh * Hh) + col] = acc;
    }
}

// ---------------------------------------------------------------------------
// qn (din=32) with packed f32x2 FMA. block = 128 threads, tile = 8 nodes x
// 1024 cols (8 cols / thread). x duplicate-packed in smem so one LDS.64 feeds
// 4 FFMA2. grid = N/8 = 1250.
// ---------------------------------------------------------------------------
__global__ void qn2_kernel(const float* __restrict__ x,
                           const float* __restrict__ w2,
                           float* __restrict__ Qn) {
    __shared__ float2 xs2[8][Hh];
    const int nbase = blockIdx.x * 8;
    const int tid = threadIdx.x;

    for (int idx = tid; idx < 8 * Hh; idx += 128) {
        int t = idx >> 5, i = idx & 31;
        float v = fmaxf(x[(nbase + t) * Hh + i], 0.f);   // relu on load
        xs2[t][i] = make_float2(v, v);
    }
    __syncthreads();

    const int c0 = tid * 8;            // 0..1016
    const int k  = c0 >> 5;
    const int ob = c0 & 31;            // 0,8,16,24
    const float* wbase = w2 + k * (Hh * Hh) + ob;

    unsigned long long acc[8][4];
#pragma unroll
    for (int t = 0; t < 8; t++)
#pragma unroll
        for (int p = 0; p < 4; p++) acc[t][p] = 0ULL;

#pragma unroll
    for (int i = 0; i < Hh; i++) {
        ulonglong2 wa = *reinterpret_cast<const ulonglong2*>(wbase + i * Hh);
        ulonglong2 wb = *reinterpret_cast<const ulonglong2*>(wbase + i * Hh + 4);
#pragma unroll
        for (int t = 0; t < 8; t++) {
            unsigned long long xv =
                *reinterpret_cast<const unsigned long long*>(&xs2[t][i]);
            asm("fma.rn.f32x2 %0,%1,%2,%0;" : "+l"(acc[t][0]) : "l"(xv), "l"(wa.x));
            asm("fma.rn.f32x2 %0,%1,%2,%0;" : "+l"(acc[t][1]) : "l"(xv), "l"(wa.y));
            asm("fma.rn.f32x2 %0,%1,%2,%0;" : "+l"(acc[t][2]) : "l"(xv), "l"(wb.x));
            asm("fma.rn.f32x2 %0,%1,%2,%0;" : "+l"(acc[t][3]) : "l"(xv), "l"(wb.y));
        }
    }

#pragma unroll
    for (int t = 0; t < 8; t++) {
        float* dst = Qn + (nbase + t) * (Hh * Hh) + c0;
#pragma unroll
        for (int p = 0; p < 4; p++)
            *reinterpret_cast<unsigned long long*>(dst + p * 2) = acc[t][p];
    }
}

// ---------------------------------------------------------------------------
// node aux: agg_init[n,o] = x[n]·root[:,o] + bias[o]
//           r[n,o]        = x[n]·b2[:,o slice]
// ---------------------------------------------------------------------------
template <int DIN, bool RELU>
__global__ void aux_kernel(const float* __restrict__ x,
                           const float* __restrict__ root,
                           const float* __restrict__ bias,
                           const float* __restrict__ b2,
                           float* __restrict__ agg,
                           float* __restrict__ rbuf) {
    int warp = (blockIdx.x * blockDim.x + threadIdx.x) >> 5;
    int lane = threadIdx.x & 31;
    if (warp >= Nn) return;
    float accA = 0.f, accR = 0.f;
#pragma unroll
    for (int i = 0; i < DIN; i++) {
        float xv = x[warp * DIN + i];
        if (RELU) xv = fmaxf(xv, 0.f);
        accA = fmaf(xv, root[i * Hh + lane], accA);
        accR = fmaf(xv, b2[i * Hh + lane], accR);
    }
    agg [warp * Hh + lane] = accA + bias[lane];
    rbuf[warp * Hh + lane] = accR;
}

// ---------------------------------------------------------------------------
// edge stage, src-sorted: one warp per NODE. Load the node's Qn row (4KB)
// into 32 regs/lane once, then loop its edges (avg degree 16) reusing it.
// ---------------------------------------------------------------------------
__global__ void edge2_kernel(const float* __restrict__ w1,
                             const float* __restrict__ b1,
                             const float* __restrict__ Qn,
                             const float* __restrict__ rbuf,
                             float* __restrict__ agg) {
    int n    = (blockIdx.x * blockDim.x + threadIdx.x) >> 5;
    int lane = threadIdx.x & 31;
    if (n >= Nn) return;
    int beg = g_off[n], end = g_off[n + 1];
    if (beg == end) return;

    const float w1a = w1[lane], w1b = w1[Hh + lane], b1v = b1[lane];

    float qreg[Hh];
    const float* __restrict__ q = Qn + n * (Hh * Hh) + lane;
#pragma unroll
    for (int k = 0; k < Hh; k++) qreg[k] = q[k * Hh];
    const float rsrc = rbuf[n * Hh + lane];

    for (int e = beg; e < end; e++) {
        float2 eav = g_sea[e];
        int dst = g_sdst[e];
        float h = fmaxf(fmaf(eav.x, w1a, fmaf(eav.y, w1b, b1v)), 0.f);

        float a0 = rsrc, a1 = 0.f, a2 = 0.f, a3 = 0.f;
#pragma unroll
        for (int k = 0; k < Hh; k += 4) {
            a0 = fmaf(__shfl_sync(0xffffffffu, h, k    ), qreg[k    ], a0);
            a1 = fmaf(__shfl_sync(0xffffffffu, h, k + 1), qreg[k + 1], a1);
            a2 = fmaf(__shfl_sync(0xffffffffu, h, k + 2), qreg[k + 2], a2);
            a3 = fmaf(__shfl_sync(0xffffffffu, h, k + 3), qreg[k + 3], a3);
        }
        atomicAdd(&agg[dst * Hh + lane], (a0 + a1) + (a2 + a3));
    }
}

// ---------------------------------------------------------------------------
// final FC + log_softmax: one warp per node
// ---------------------------------------------------------------------------
__global__ void fc_kernel(const float* __restrict__ xr,
                          const float* __restrict__ fcw,
                          const float* __restrict__ fcb,
                          float* __restrict__ out) {
    int warp = (blockIdx.x * blockDim.x + threadIdx.x) >> 5;
    int lane = threadIdx.x & 31;
    if (warp >= Nn) return;

    float xv = fmaxf(xr[warp * Hh + lane], 0.f);
    float lg[Cc];
#pragma unroll
    for (int c = 0; c < Cc; c++) {
        float p = xv * fcw[lane * Cc + c];
#pragma unroll
        for (int s = 16; s > 0; s >>= 1)
            p += __shfl_xor_sync(0xffffffffu, p, s);
        lg[c] = p + fcb[c];
    }
    float m = fmaxf(fmaxf(lg[0], lg[1]), fmaxf(lg[2], lg[3]));
    float se = 0.f;
#pragma unroll
    for (int c = 0; c < Cc; c++) se += __expf(lg[c] - m);
    float lse = m + __logf(se);
    if (lane < Cc) out[warp * Cc + lane] = lg[lane] - lse;
}

// ---------------------------------------------------------------------------
extern "C" void kernel_launch(void* const* d_in, const int* in_sizes, int n_in,
                              void* d_out, int out_size) {
    (void)in_sizes; (void)n_in; (void)out_size;

    const float* x  = (const float*)d_in[0];
    const int*   ei = (const int*)  d_in[1];
    const float* ea = (const float*)d_in[2];
    const float* w1[3];  const float* b1[3];  const float* w2[3];
    const float* b2[3];  const float* rt[3];  const float* bs[3];
    for (int l = 0; l < 3; l++) {
        w1[l] = (const float*)d_in[3 + 6 * l + 0];
        b1[l] = (const float*)d_in[3 + 6 * l + 1];
        w2[l] = (const float*)d_in[3 + 6 * l + 2];
        b2[l] = (const float*)d_in[3 + 6 * l + 3];
        rt[l] = (const float*)d_in[3 + 6 * l + 4];
        bs[l] = (const float*)d_in[3 + 6 * l + 5];
    }
    const float* fcw = (const float*)d_in[21];
    const float* fcb = (const float*)d_in[22];
    float* out = (float*)d_out;

    float *Qn, *rbuf, *xA, *xB;
    cudaGetSymbolAddress((void**)&Qn,   g_Qn);
    cudaGetSymbolAddress((void**)&rbuf, g_r);
    cudaGetSymbolAddress((void**)&xA,   g_xA);
    cudaGetSymbolAddress((void**)&xB,   g_xB);

    const dim3 q0grid((Nn + 15) / 16, 4);
    const int  qn2Blocks      = Nn / 8;                    // 1250
    const int  nodeWarpBlocks = (Nn * 32 + 255) / 256;     // 1250
    const int  eThreads       = (Ee + 255) / 256;          // for hist/scatter

    // ---------------- counting sort of edges by src ---------------------
    zero_kernel<<<(Nn + 1023) / 1024, 1024>>>();
    hist_kernel<<<eThreads, 256>>>(ei);
    scan_kernel<<<1, 1024>>>();
    scatter_kernel<<<eThreads, 256>>>(ei, ea);

    // ---------------- layer 0 (din=4, input not relu'd) ----------------
    qn0_kernel<<<q0grid, 256>>>(x, w2[0], Qn);
    aux_kernel<Ff, false><<<nodeWarpBlocks, 256>>>(x, rt[0], bs[0], b2[0], xA, rbuf);
    edge2_kernel<<<nodeWarpBlocks, 256>>>(w1[0], b1[0], Qn, rbuf, xA);

    // ---------------- layer 1 -------------------------------------------
    qn2_kernel<<<qn2Blocks, 128>>>(xA, w2[1], Qn);
    aux_kernel<Hh, true><<<nodeWarpBlocks, 256>>>(xA, rt[1], bs[1], b2[1], xB, rbuf);
    edge2_kernel<<<nodeWarpBlocks, 256>>>(w1[1], b1[1], Qn, rbuf, xB);

    // ---------------- layer 2 -------------------------------------------
    qn2_kernel<<<qn2Blocks, 128>>>(xB, w2[2], Qn);
    aux_kernel<Hh, true><<<nodeWarpBlocks, 256>>>(xB, rt[2], bs[2], b2[2], xA, rbuf);
    edge2_kernel<<<nodeWarpBlocks, 256>>>(w1[2], b1[2], Qn, rbuf, xA);

    // ---------------- FC + log_softmax ----------------------------------
    fc_kernel<<<nodeWarpBlocks, 256>>>(xA, fcw, fcb, out);
}

// round 3
// speedup vs baseline: 1.2099x; 1.1408x over previous
#include <cuda_runtime.h>
#include <math.h>

#define Nn 10000
#define Ee 160000
#define Ff 4
#define Hh 32
#define Cc 4

// ---------------- scratch (device globals; no allocation allowed) -----------
__device__ float g_Qn[Nn * Hh * Hh];       // per-node Q matrices [N, H, H] (40MB)
__device__ float g_r [Nn * Hh];            // per-node b2 contribution r[n,o]
__device__ float g_xA[Nn * Hh];            // ping-pong node features (pre-relu)
__device__ float g_xB[Nn * Hh];
__device__ int    g_cnt[Nn];               // counting sort: histogram
__device__ int    g_cur[Nn];               // counting sort: scatter cursors
__device__ int    g_off[Nn + 1];           // CSR offsets by src
__device__ int    g_sdst[Ee];              // dst sorted by src
__device__ float2 g_sea [Ee];              // edge_attr sorted by src

// ---------------------------------------------------------------------------
// counting sort by src
// ---------------------------------------------------------------------------
__global__ void zero_kernel() {
    int t = blockIdx.x * blockDim.x + threadIdx.x;
    if (t < Nn) { g_cnt[t] = 0; g_cur[t] = 0; }
}

__global__ void hist_kernel(const int* __restrict__ ei) {
    int base = (blockIdx.x * blockDim.x + threadIdx.x) * 4;
#pragma unroll
    for (int j = 0; j < 4; j++) {
        int t = base + j;
        if (t < Ee) atomicAdd(&g_cnt[ei[t]], 1);
    }
}

__global__ void scan_kernel() {
    __shared__ int partial[1024];
    const int tid = threadIdx.x;
    const int base = tid * 10;                 // 1024*10 = 10240 >= 10000
    int s = 0;
    for (int j = 0; j < 10; j++) {
        int idx = base + j;
        if (idx < Nn) s += g_cnt[idx];
    }
    partial[tid] = s;
    __syncthreads();
    for (int d = 1; d < 1024; d <<= 1) {       // Hillis-Steele inclusive scan
        int v = 0;
        if (tid >= d) v = partial[tid - d];
        __syncthreads();
        if (tid >= d) partial[tid] += v;
        __syncthreads();
    }
    int run = (tid > 0) ? partial[tid - 1] : 0;
    for (int j = 0; j < 10; j++) {
        int idx = base + j;
        if (idx < Nn) { g_off[idx] = run; run += g_cnt[idx]; }
    }
    if (tid == 1023) g_off[Nn] = run;          // == Ee
}

__global__ void scatter_kernel(const int* __restrict__ ei,
                               const float* __restrict__ ea) {
    int base = (blockIdx.x * blockDim.x + threadIdx.x) * 4;
#pragma unroll
    for (int j = 0; j < 4; j++) {
        int t = base + j;
        if (t < Ee) {
            int s = ei[t];
            int p = g_off[s] + atomicAdd(&g_cur[s], 1);
            g_sdst[p] = ei[Ee + t];
            g_sea[p]  = reinterpret_cast<const float2*>(ea)[t];
        }
    }
}

// ---------------------------------------------------------------------------
// fused Qn + aux:  Qn[n,k*32+o] = sum_i x'[n,i]*w2[k,i*32+o]   (x' = relu?(x))
//                  agg[n,o]     = sum_i x'[n,i]*root[i,o] + bias[o]
//                  rbuf[n,o]    = sum_i x'[n,i]*b2[i*32+o]
// block = 128 threads, 8 nodes/block, 8 Q-cols/thread, f32x2 FMA.
// ---------------------------------------------------------------------------
template <int DIN, bool RELU>
__global__ void qnaux_kernel(const float* __restrict__ x,
                             const float* __restrict__ w2,
                             const float* __restrict__ root,
                             const float* __restrict__ bias,
                             const float* __restrict__ b2,
                             float* __restrict__ Qn,
                             float* __restrict__ agg,
                             float* __restrict__ rbuf) {
    __shared__ float2 xs2[8][DIN];
    const int nbase = blockIdx.x * 8;
    const int tid = threadIdx.x;

    for (int idx = tid; idx < 8 * DIN; idx += 128) {
        int t = idx / DIN, i = idx % DIN;
        float v = x[(nbase + t) * DIN + i];
        if (RELU) v = fmaxf(v, 0.f);
        xs2[t][i] = make_float2(v, v);
    }
    __syncthreads();

    const int c0 = tid * 8;            // 0..1016
    const int k  = c0 >> 5;
    const int ob = c0 & 31;
    const float* wbase = w2 + k * (DIN * Hh) + ob;

    unsigned long long acc[8][4];
#pragma unroll
    for (int t = 0; t < 8; t++)
#pragma unroll
        for (int p = 0; p < 4; p++) acc[t][p] = 0ULL;

#pragma unroll
    for (int i = 0; i < DIN; i++) {
        ulonglong2 wa = *reinterpret_cast<const ulonglong2*>(wbase + i * Hh);
        ulonglong2 wb = *reinterpret_cast<const ulonglong2*>(wbase + i * Hh + 4);
#pragma unroll
        for (int t = 0; t < 8; t++) {
            unsigned long long xv =
                *reinterpret_cast<const unsigned long long*>(&xs2[t][i]);
            asm("fma.rn.f32x2 %0,%1,%2,%0;" : "+l"(acc[t][0]) : "l"(xv), "l"(wa.x));
            asm("fma.rn.f32x2 %0,%1,%2,%0;" : "+l"(acc[t][1]) : "l"(xv), "l"(wa.y));
            asm("fma.rn.f32x2 %0,%1,%2,%0;" : "+l"(acc[t][2]) : "l"(xv), "l"(wb.x));
            asm("fma.rn.f32x2 %0,%1,%2,%0;" : "+l"(acc[t][3]) : "l"(xv), "l"(wb.y));
        }
    }

#pragma unroll
    for (int t = 0; t < 8; t++) {
        float* dst = Qn + (nbase + t) * (Hh * Hh) + c0;
#pragma unroll
        for (int p = 0; p < 4; p++)
            *reinterpret_cast<unsigned long long*>(dst + p * 2) = acc[t][p];
    }

    // ---- aux part: 8 nodes x 32 outputs = 256 items over 128 threads ----
    for (int it = tid; it < 256; it += 128) {
        int t = it >> 5, o = it & 31;
        float accA = 0.f, accR = 0.f;
#pragma unroll
        for (int i = 0; i < DIN; i++) {
            float xv = xs2[t][i].x;
            accA = fmaf(xv, root[i * Hh + o], accA);
            accR = fmaf(xv, b2  [i * Hh + o], accR);
        }
        agg [(nbase + t) * Hh + o] = accA + bias[o];
        rbuf[(nbase + t) * Hh + o] = accR;
    }
}

// ---------------------------------------------------------------------------
// edge stage, src-sorted: one warp per node, 32-edge tiles.
// Phase 1: compute h for the tile (2 shfl + 3 fma + 1 STS per edge).
// Phase 2: 8x LDS.128 broadcast + 32 FMA + 1 RED per edge.
// ---------------------------------------------------------------------------
__global__ void edge3_kernel(const float* __restrict__ w1,
                             const float* __restrict__ b1,
                             const float* __restrict__ Qn,
                             const float* __restrict__ rbuf,
                             float* __restrict__ agg) {
    __shared__ float hs_all[8][32][32];        // 32KB: per-warp h tile
    const int wip  = threadIdx.x >> 5;
    const int n    = (blockIdx.x * blockDim.x + threadIdx.x) >> 5;
    const int lane = threadIdx.x & 31;
    if (n >= Nn) return;
    const int beg = g_off[n], end = g_off[n + 1];
    if (beg == end) return;
    float (*hs)[32] = hs_all[wip];

    const float w1a = w1[lane], w1b = w1[Hh + lane], b1v = b1[lane];

    float qreg[Hh];
    const float* __restrict__ q = Qn + n * (Hh * Hh) + lane;
#pragma unroll
    for (int k = 0; k < Hh; k++) qreg[k] = q[k * Hh];
    const float rsrc = rbuf[n * Hh + lane];

    for (int t = beg; t < end; t += 32) {
        const int m = min(32, end - t);
        float2 eav = make_float2(0.f, 0.f);
        int dstv = 0;
        if (lane < m) { eav = g_sea[t + lane]; dstv = g_sdst[t + lane]; }

        // phase 1: h for each edge in tile (lane = k)
        for (int e = 0; e < m; e++) {
            float ea0 = __shfl_sync(0xffffffffu, eav.x, e);
            float ea1 = __shfl_sync(0xffffffffu, eav.y, e);
            hs[e][lane] = fmaxf(fmaf(ea0, w1a, fmaf(ea1, w1b, b1v)), 0.f);
        }
        __syncwarp();

        // phase 2: msg = r + Q^T h, scatter
        for (int e = 0; e < m; e++) {
            int dst = __shfl_sync(0xffffffffu, dstv, e);
            const float4* hv = reinterpret_cast<const float4*>(hs[e]);
            float a0 = rsrc, a1 = 0.f, a2 = 0.f, a3 = 0.f;
#pragma unroll
            for (int c = 0; c < 8; c++) {
                float4 h4 = hv[c];
                a0 = fmaf(h4.x, qreg[4 * c    ], a0);
                a1 = fmaf(h4.y, qreg[4 * c + 1], a1);
                a2 = fmaf(h4.z, qreg[4 * c + 2], a2);
                a3 = fmaf(h4.w, qreg[4 * c + 3], a3);
            }
            atomicAdd(&agg[dst * Hh + lane], (a0 + a1) + (a2 + a3));
        }
        __syncwarp();
    }
}

// ---------------------------------------------------------------------------
// final FC + log_softmax: one warp per node
// ---------------------------------------------------------------------------
__global__ void fc_kernel(const float* __restrict__ xr,
                          const float* __restrict__ fcw,
                          const float* __restrict__ fcb,
                          float* __restrict__ out) {
    int warp = (blockIdx.x * blockDim.x + threadIdx.x) >> 5;
    int lane = threadIdx.x & 31;
    if (warp >= Nn) return;

    float xv = fmaxf(xr[warp * Hh + lane], 0.f);
    float lg[Cc];
#pragma unroll
    for (int c = 0; c < Cc; c++) {
        float p = xv * fcw[lane * Cc + c];
#pragma unroll
        for (int s = 16; s > 0; s >>= 1)
            p += __shfl_xor_sync(0xffffffffu, p, s);
        lg[c] = p + fcb[c];
    }
    float m = fmaxf(fmaxf(lg[0], lg[1]), fmaxf(lg[2], lg[3]));
    float se = 0.f;
#pragma unroll
    for (int c = 0; c < Cc; c++) se += __expf(lg[c] - m);
    float lse = m + __logf(se);
    if (lane < Cc) out[warp * Cc + lane] = lg[lane] - lse;
}

// ---------------------------------------------------------------------------
extern "C" void kernel_launch(void* const* d_in, const int* in_sizes, int n_in,
                              void* d_out, int out_size) {
    (void)in_sizes; (void)n_in; (void)out_size;

    const float* x  = (const float*)d_in[0];
    const int*   ei = (const int*)  d_in[1];
    const float* ea = (const float*)d_in[2];
    const float* w1[3];  const float* b1[3];  const float* w2[3];
    const float* b2[3];  const float* rt[3];  const float* bs[3];
    for (int l = 0; l < 3; l++) {
        w1[l] = (const float*)d_in[3 + 6 * l + 0];
        b1[l] = (const float*)d_in[3 + 6 * l + 1];
        w2[l] = (const float*)d_in[3 + 6 * l + 2];
        b2[l] = (const float*)d_in[3 + 6 * l + 3];
        rt[l] = (const float*)d_in[3 + 6 * l + 4];
        bs[l] = (const float*)d_in[3 + 6 * l + 5];
    }
    const float* fcw = (const float*)d_in[21];
    const float* fcb = (const float*)d_in[22];
    float* out = (float*)d_out;

    float *Qn, *rbuf, *xA, *xB;
    cudaGetSymbolAddress((void**)&Qn,   g_Qn);
    cudaGetSymbolAddress((void**)&rbuf, g_r);
    cudaGetSymbolAddress((void**)&xA,   g_xA);
    cudaGetSymbolAddress((void**)&xB,   g_xB);

    const int qnBlocks        = Nn / 8;                    // 1250
    const int nodeWarpBlocks  = (Nn * 32 + 255) / 256;     // 1250
    const int e4Blocks        = (Ee / 4 + 255) / 256;      // 157

    // ---------------- counting sort of edges by src ---------------------
    zero_kernel<<<(Nn + 1023) / 1024, 1024>>>();
    hist_kernel<<<e4Blocks, 256>>>(ei);
    scan_kernel<<<1, 1024>>>();
    scatter_kernel<<<e4Blocks, 256>>>(ei, ea);

    // ---------------- layer 0 (din=4, input not relu'd) ----------------
    qnaux_kernel<Ff, false><<<qnBlocks, 128>>>(x,  w2[0], rt[0], bs[0], b2[0], Qn, xA, rbuf);
    edge3_kernel<<<nodeWarpBlocks, 256>>>(w1[0], b1[0], Qn, rbuf, xA);

    // ---------------- layer 1 -------------------------------------------
    qnaux_kernel<Hh, true ><<<qnBlocks, 128>>>(xA, w2[1], rt[1], bs[1], b2[1], Qn, xB, rbuf);
    edge3_kernel<<<nodeWarpBlocks, 256>>>(w1[1], b1[1], Qn, rbuf, xB);

    // ---------------- layer 2 -------------------------------------------
    qnaux_kernel<Hh, true ><<<qnBlocks, 128>>>(xB, w2[2], rt[2], bs[2], b2[2], Qn, xA, rbuf);
    edge3_kernel<<<nodeWarpBlocks, 256>>>(w1[2], b1[2], Qn, rbuf, xA);

    // ---------------- FC + log_softmax ----------------------------------
    fc_kernel<<<nodeWarpBlocks, 256>>>(xA, fcw, fcb, out);
}